// round 2
// baseline (speedup 1.0000x reference)
#include <cuda_runtime.h>
#include <cuda_bf16.h>
#include <cstdint>

// ============================================================================
// y = x @ W_binT - rowmean(y),  B=131072, IN=OUT=256.
// Trick 1: fold mean into weights: W' = W_bin - c/256 (exact in bf16).
// Trick 2: x = hi + lo bf16 split, 2 accumulating HMMA per k-step (fp32-exact).
// Baseline-ISA implementation (mma.sync + ldmatrix) since compute_103 PTX
// target has no tcgen05.
// ============================================================================

static constexpr int INF    = 256;
static constexpr int OUTF   = 256;
static constexpr int BATCH  = 131072;
static constexpr int MTILE  = 128;
static constexpr int NTILES = BATCH / MTILE;   // 1024
static constexpr int GRID   = 148;
static constexpr int THREADS = 256;

static constexpr int PW = 264;   // W smem pitch in bf16 (264*2=528B, conflict-free)
static constexpr int PA = 72;    // A smem pitch in bf16 (144B, conflict-free)
static constexpr int WBYTES = OUTF * PW * 2;        // 135168
static constexpr int ABYTES = MTILE * PA * 2;       // 18432
static constexpr int SMEM_TOTAL = WBYTES + 2 * ABYTES;  // 172032

__device__ __nv_bfloat16 g_wprep[OUTF * PW];  // mean-folded W, padded layout
__device__ float g_colscale[INF];             // c_i / 256

// ---------------------------------------------------------------------------
// prep kernels
// ---------------------------------------------------------------------------
__global__ void prep_counts_k(const float* __restrict__ w) {
    __shared__ int red[256];
    const int i = blockIdx.x, t = threadIdx.x;
    red[t] = (w[t * INF + i] > 0.8f) ? 1 : 0;
    __syncthreads();
    #pragma unroll
    for (int s = 128; s > 0; s >>= 1) {
        if (t < s) red[t] += red[t + s];
        __syncthreads();
    }
    if (t == 0) g_colscale[i] = (float)red[0] * (1.0f / 256.0f);  // exact
}

__global__ void prep_w_k(const float* __restrict__ w) {
    const int o = blockIdx.x, i = threadIdx.x;
    float v = ((w[o * INF + i] > 0.8f) ? 1.0f : 0.0f) - g_colscale[i];
    g_wprep[o * PW + i] = __float2bfloat16(v);  // exact: n/256, |n|<=256
}

// ---------------------------------------------------------------------------
// main GEMM
// ---------------------------------------------------------------------------
#define MMA_BF16(c, a, b0, b1)                                                 \
    asm volatile(                                                              \
        "mma.sync.aligned.m16n8k16.row.col.f32.bf16.bf16.f32 "                 \
        "{%0,%1,%2,%3},{%4,%5,%6,%7},{%8,%9},{%0,%1,%2,%3};"                   \
        : "+f"((c)[0]), "+f"((c)[1]), "+f"((c)[2]), "+f"((c)[3])               \
        : "r"((a)[0]), "r"((a)[1]), "r"((a)[2]), "r"((a)[3]),                  \
          "r"(b0), "r"(b1))

#define LDSM4(r, addr)                                                         \
    asm volatile("ldmatrix.sync.aligned.m8n8.x4.shared.b16 {%0,%1,%2,%3}, [%4];" \
        : "=r"((r)[0]), "=r"((r)[1]), "=r"((r)[2]), "=r"((r)[3]) : "r"(addr))

__global__ void __launch_bounds__(THREADS, 1)
bgemm_kernel(const float* __restrict__ x, float* __restrict__ out)
{
    extern __shared__ char smem[];
    const int tid  = threadIdx.x;
    const int lane = tid & 31;
    const int wid  = tid >> 5;
    const int wm   = (wid & 1) * 64;   // warp m-offset in tile
    const int wn   = (wid >> 1) * 64;  // warp n-offset

    // ---- copy resident W' into smem (stays for whole kernel)
    {
        const uint4* src = reinterpret_cast<const uint4*>(g_wprep);
        uint4* dst = reinterpret_cast<uint4*>(smem);
        #pragma unroll
        for (int k = 0; k < WBYTES / 16 / THREADS; ++k)
            dst[tid + k * THREADS] = src[tid + k * THREADS];
    }

    uint32_t sb;
    asm("{ .reg .u64 t; cvta.to.shared.u64 t, %1; cvt.u32.u64 %0, t; }"
        : "=r"(sb) : "l"(smem));
    const uint32_t AH = sb + WBYTES;
    const uint32_t AL = AH + ABYTES;

    // per-thread ldmatrix source offsets (bytes)
    const uint32_t aoff =
        (uint32_t)((wm + (lane & 15)) * PA + (lane >> 4) * 8) * 2u;
    const uint32_t boff =
        (uint32_t)((wn + ((lane >> 4) & 1) * 8 + (lane & 7)) * PW +
                   ((lane >> 3) & 1) * 8) * 2u;

    const int xrow = tid >> 1;          // 0..127
    const int xkb  = (tid & 1) * 32;    // 0 or 32 (floats)

    float4 xr[8];
    // prologue prefetch: tile=blockIdx.x, chunk 0
    {
        const float4* gp = reinterpret_cast<const float4*>(
            x + ((size_t)(blockIdx.x * MTILE + xrow)) * INF + xkb);
        #pragma unroll
        for (int j = 0; j < 8; ++j) xr[j] = gp[j];
    }

    for (int tile = blockIdx.x; tile < NTILES; tile += GRID) {
        float acc[4][8][4];
        #pragma unroll
        for (int a = 0; a < 4; ++a)
            #pragma unroll
            for (int b = 0; b < 8; ++b)
                #pragma unroll
                for (int q = 0; q < 4; ++q) acc[a][b][q] = 0.0f;

        for (int ch = 0; ch < 4; ++ch) {
            __syncthreads();   // previous chunk's ldmatrix reads done
            // ---- convert fp32 -> hi/lo bf16, STS
            {
                const uint32_t base = (uint32_t)(xrow * PA + xkb);
                #pragma unroll
                for (int j = 0; j < 8; ++j) {
                    float4 v = xr[j];
                    uint32_t h0, h1, l0, l1;
                    asm("cvt.rn.bf16x2.f32 %0, %1, %2;" : "=r"(h0) : "f"(v.y), "f"(v.x));
                    asm("cvt.rn.bf16x2.f32 %0, %1, %2;" : "=r"(h1) : "f"(v.w), "f"(v.z));
                    float rx = v.x - __uint_as_float(h0 << 16);
                    float ry = v.y - __uint_as_float(h0 & 0xFFFF0000u);
                    float rz = v.z - __uint_as_float(h1 << 16);
                    float rw = v.w - __uint_as_float(h1 & 0xFFFF0000u);
                    asm("cvt.rn.bf16x2.f32 %0, %1, %2;" : "=r"(l0) : "f"(ry), "f"(rx));
                    asm("cvt.rn.bf16x2.f32 %0, %1, %2;" : "=r"(l1) : "f"(rw), "f"(rz));
                    uint32_t off = (base + 4u * j) * 2u;
                    asm volatile("st.shared.v2.b32 [%0], {%1,%2};"
                                 :: "r"(AH + off), "r"(h0), "r"(h1));
                    asm volatile("st.shared.v2.b32 [%0], {%1,%2};"
                                 :: "r"(AL + off), "r"(l0), "r"(l1));
                }
            }
            __syncthreads();   // A tile visible

            // ---- prefetch next chunk (possibly next tile) into registers
            {
                int nt = tile, nc = ch + 1;
                if (nc == 4) { nt = tile + GRID; nc = 0; }
                if (nt < NTILES) {
                    const float4* gp = reinterpret_cast<const float4*>(
                        x + ((size_t)(nt * MTILE + xrow)) * INF + nc * 64 + xkb);
                    #pragma unroll
                    for (int j = 0; j < 8; ++j) xr[j] = gp[j];
                }
            }

            // ---- MMA over this K-chunk (4 k16-steps)
            const uint32_t bko = (uint32_t)(ch * 64) * 2u;
            #pragma unroll
            for (int ks = 0; ks < 4; ++ks) {
                const uint32_t kb2 = (uint32_t)(ks * 16) * 2u;
                uint32_t bfr[4][4];
                #pragma unroll
                for (int np = 0; np < 4; ++np)
                    LDSM4(bfr[np], sb + boff + (uint32_t)(np * 16 * PW * 2) + bko + kb2);

                uint32_t af[4][4];
                #pragma unroll
                for (int mi = 0; mi < 4; ++mi)
                    LDSM4(af[mi], AH + aoff + (uint32_t)(mi * 16 * PA * 2) + kb2);
                #pragma unroll
                for (int mi = 0; mi < 4; ++mi)
                    #pragma unroll
                    for (int ni = 0; ni < 8; ++ni)
                        MMA_BF16(acc[mi][ni], af[mi],
                                 bfr[ni >> 1][(ni & 1) * 2],
                                 bfr[ni >> 1][(ni & 1) * 2 + 1]);

                #pragma unroll
                for (int mi = 0; mi < 4; ++mi)
                    LDSM4(af[mi], AL + aoff + (uint32_t)(mi * 16 * PA * 2) + kb2);
                #pragma unroll
                for (int mi = 0; mi < 4; ++mi)
                    #pragma unroll
                    for (int ni = 0; ni < 8; ++ni)
                        MMA_BF16(acc[mi][ni], af[mi],
                                 bfr[ni >> 1][(ni & 1) * 2],
                                 bfr[ni >> 1][(ni & 1) * 2 + 1]);
            }
        }

        // ---- epilogue: regs -> gmem (mean already folded into W')
        const int g  = lane >> 2;
        const int t4 = (lane & 3) * 2;
        #pragma unroll
        for (int mi = 0; mi < 4; ++mi) {
            size_t r0 = (size_t)(tile * MTILE + wm + mi * 16 + g) * OUTF;
            #pragma unroll
            for (int ni = 0; ni < 8; ++ni) {
                int col = wn + ni * 8 + t4;
                *reinterpret_cast<float2*>(out + r0 + col) =
                    make_float2(acc[mi][ni][0], acc[mi][ni][1]);
                *reinterpret_cast<float2*>(out + r0 + 8 * OUTF + col) =
                    make_float2(acc[mi][ni][2], acc[mi][ni][3]);
            }
        }
    }
}

// ---------------------------------------------------------------------------
extern "C" void kernel_launch(void* const* d_in, const int* in_sizes, int n_in,
                              void* d_out, int out_size) {
    const float* x = (const float*)d_in[0];
    const float* w = (const float*)d_in[1];
    if (n_in >= 2 && in_sizes[0] < in_sizes[1]) {  // defensive: x is the big one
        const float* t = x; x = w; w = t;
    }
    float* out = (float*)d_out;

    prep_counts_k<<<256, 256>>>(w);
    prep_w_k<<<256, 256>>>(w);

    cudaFuncSetAttribute(bgemm_kernel,
                         cudaFuncAttributeMaxDynamicSharedMemorySize, SMEM_TOTAL);
    bgemm_kernel<<<GRID, THREADS, SMEM_TOTAL>>>(x, out);
}

// round 3
// speedup vs baseline: 1.2102x; 1.2102x over previous
#include <cuda_runtime.h>
#include <cuda_fp16.h>
#include <cstdint>

// ============================================================================
// y = x @ W_binT - rowmean(y),  B=131072, IN=OUT=256.
// Trick 1: fold mean into weights: W' = W_bin - c/256 (EXACT in fp16: n/256).
// Trick 2: single fp16 pass for x (unit roundoff 2^-11 -> global rel err ~3e-4,
//          threshold 1e-3). Halves tensor work vs bf16 hi/lo split, and the
//          legacy mma.sync pipe (~305 TF/s measured) is the binding resource.
// Double-buffered A tile: convert+STS of chunk c+1 overlaps MMA of chunk c.
// ============================================================================

static constexpr int INF    = 256;
static constexpr int OUTF   = 256;
static constexpr int BATCH  = 131072;
static constexpr int MTILE  = 128;
static constexpr int NTILES = BATCH / MTILE;   // 1024
static constexpr int GRID   = 148;
static constexpr int THREADS = 256;

static constexpr int PW = 264;   // W smem pitch (halfs), 528B rows, conflict-free
static constexpr int PA = 72;    // A smem pitch (halfs), 144B rows, conflict-free
static constexpr int WBYTES = OUTF * PW * 2;        // 135168
static constexpr int ABYTES = MTILE * PA * 2;       // 18432
static constexpr int SMEM_TOTAL = WBYTES + 2 * ABYTES;  // 172032

__device__ __half g_wprep[OUTF * PW];   // mean-folded W', padded layout
__device__ int    g_colcnt[INF];

// ---------------------------------------------------------------------------
// prep kernels (coalesced; counts via spread-address atomics)
// ---------------------------------------------------------------------------
__global__ void zero_k() { g_colcnt[threadIdx.x] = 0; }

__global__ void count_k(const float* __restrict__ w) {
    const int o = blockIdx.x, i = threadIdx.x;
    if (w[o * INF + i] > 0.8f) atomicAdd(&g_colcnt[i], 1);
}

__global__ void fold_k(const float* __restrict__ w) {
    const int o = blockIdx.x, i = threadIdx.x;
    float v = ((w[o * INF + i] > 0.8f) ? 1.0f : 0.0f)
              - (float)g_colcnt[i] * (1.0f / 256.0f);
    g_wprep[o * PW + i] = __float2half_rn(v);   // exact: n/256, |n| <= 256
}

// ---------------------------------------------------------------------------
// main GEMM
// ---------------------------------------------------------------------------
#define MMA_F16(c, a, b0, b1)                                                  \
    asm volatile(                                                              \
        "mma.sync.aligned.m16n8k16.row.col.f32.f16.f16.f32 "                   \
        "{%0,%1,%2,%3},{%4,%5,%6,%7},{%8,%9},{%0,%1,%2,%3};"                   \
        : "+f"((c)[0]), "+f"((c)[1]), "+f"((c)[2]), "+f"((c)[3])               \
        : "r"((a)[0]), "r"((a)[1]), "r"((a)[2]), "r"((a)[3]),                  \
          "r"(b0), "r"(b1))

#define LDSM4(r, addr)                                                         \
    asm volatile("ldmatrix.sync.aligned.m8n8.x4.shared.b16 {%0,%1,%2,%3}, [%4];" \
        : "=r"((r)[0]), "=r"((r)[1]), "=r"((r)[2]), "=r"((r)[3]) : "r"(addr))

__global__ void __launch_bounds__(THREADS, 1)
bgemm_kernel(const float* __restrict__ x, float* __restrict__ out)
{
    extern __shared__ char smem[];
    const int tid  = threadIdx.x;
    const int lane = tid & 31;
    const int wid  = tid >> 5;
    const int wm   = (wid & 1) * 64;   // warp m-offset
    const int wn   = (wid >> 1) * 64;  // warp n-offset

    // ---- resident W' into smem (whole kernel lifetime)
    {
        const uint4* src = reinterpret_cast<const uint4*>(g_wprep);
        uint4* dst = reinterpret_cast<uint4*>(smem);
        #pragma unroll
        for (int k = 0; k < WBYTES / 16 / THREADS; ++k)
            dst[tid + k * THREADS] = src[tid + k * THREADS];
    }

    uint32_t sb;
    asm("{ .reg .u64 t; cvta.to.shared.u64 t, %1; cvt.u32.u64 %0, t; }"
        : "=r"(sb) : "l"(smem));
    const uint32_t ABUF[2] = { sb + WBYTES, sb + WBYTES + ABYTES };

    // per-thread ldmatrix source offsets (bytes)
    const uint32_t aoff =
        (uint32_t)((wm + (lane & 15)) * PA + (lane >> 4) * 8) * 2u;
    const uint32_t boff =
        (uint32_t)((wn + ((lane >> 4) & 1) * 8 + (lane & 7)) * PW +
                   ((lane >> 3) & 1) * 8) * 2u;

    const int xrow = tid >> 1;          // 0..127
    const int xkb  = (tid & 1) * 32;    // 0 or 32 (elements)

    float4 xr[8];

    // register chunk -> fp16 -> STS into buffer b
    auto sts_chunk = [&](uint32_t ab) {
        const uint32_t base = (uint32_t)(xrow * PA + xkb) * 2u;
        #pragma unroll
        for (int j = 0; j < 8; j += 2) {
            uint32_t h0, h1, h2, h3;
            asm("cvt.rn.f16x2.f32 %0, %1, %2;" : "=r"(h0) : "f"(xr[j].y),   "f"(xr[j].x));
            asm("cvt.rn.f16x2.f32 %0, %1, %2;" : "=r"(h1) : "f"(xr[j].w),   "f"(xr[j].z));
            asm("cvt.rn.f16x2.f32 %0, %1, %2;" : "=r"(h2) : "f"(xr[j+1].y), "f"(xr[j+1].x));
            asm("cvt.rn.f16x2.f32 %0, %1, %2;" : "=r"(h3) : "f"(xr[j+1].w), "f"(xr[j+1].z));
            asm volatile("st.shared.v4.b32 [%0], {%1,%2,%3,%4};"
                         :: "r"(ab + base + 8u * j), "r"(h0), "r"(h1), "r"(h2), "r"(h3));
        }
    };
    auto ldg_chunk = [&](int nt, int nc) {
        if (nt < NTILES) {
            const float4* gp = reinterpret_cast<const float4*>(
                x + ((size_t)(nt * MTILE + xrow)) * INF + nc * 64 + xkb);
            #pragma unroll
            for (int j = 0; j < 8; ++j) xr[j] = gp[j];
        }
    };

    // prologue: chunk0 -> buf0; preload chunk1 regs
    ldg_chunk(blockIdx.x, 0);
    sts_chunk(ABUF[0]);
    ldg_chunk(blockIdx.x, 1);
    __syncthreads();

    for (int tile = blockIdx.x; tile < NTILES; tile += GRID) {
        float acc[4][8][4];
        #pragma unroll
        for (int a = 0; a < 4; ++a)
            #pragma unroll
            for (int b = 0; b < 8; ++b)
                #pragma unroll
                for (int q = 0; q < 4; ++q) acc[a][b][q] = 0.0f;

        #pragma unroll
        for (int ch = 0; ch < 4; ++ch) {
            // STS chunk ch+1 (regs already loaded) into the other buffer;
            // overlaps with MMA(ch) of other warps.
            const bool has_next = !(ch == 3 && tile + GRID >= NTILES);
            if (has_next) sts_chunk(ABUF[(ch + 1) & 1]);

            // prefetch regs for chunk ch+2
            {
                int nt = tile, nc = ch + 2;
                if (nc >= 4) { nc -= 4; nt += GRID; }
                ldg_chunk(nt, nc);
            }

            // MMA over chunk ch (4 k16-steps) from buf[ch&1]
            const uint32_t AB  = ABUF[ch & 1];
            const uint32_t bko = (uint32_t)(ch * 64) * 2u;
            #pragma unroll
            for (int ks = 0; ks < 4; ++ks) {
                const uint32_t kb2 = (uint32_t)(ks * 16) * 2u;
                uint32_t bfr[4][4];
                #pragma unroll
                for (int np = 0; np < 4; ++np)
                    LDSM4(bfr[np], sb + boff + (uint32_t)(np * 16 * PW * 2) + bko + kb2);
                uint32_t af[4][4];
                #pragma unroll
                for (int mi = 0; mi < 4; ++mi)
                    LDSM4(af[mi], AB + aoff + (uint32_t)(mi * 16 * PA * 2) + kb2);
                #pragma unroll
                for (int mi = 0; mi < 4; ++mi)
                    #pragma unroll
                    for (int ni = 0; ni < 8; ++ni)
                        MMA_F16(acc[mi][ni], af[mi],
                                bfr[ni >> 1][(ni & 1) * 2],
                                bfr[ni >> 1][(ni & 1) * 2 + 1]);
            }
            __syncthreads();
        }

        // ---- epilogue: regs -> gmem (mean already folded into W')
        const int g  = lane >> 2;
        const int t4 = (lane & 3) * 2;
        #pragma unroll
        for (int mi = 0; mi < 4; ++mi) {
            size_t r0 = (size_t)(tile * MTILE + wm + mi * 16 + g) * OUTF;
            #pragma unroll
            for (int ni = 0; ni < 8; ++ni) {
                int col = wn + ni * 8 + t4;
                *reinterpret_cast<float2*>(out + r0 + col) =
                    make_float2(acc[mi][ni][0], acc[mi][ni][1]);
                *reinterpret_cast<float2*>(out + r0 + 8 * OUTF + col) =
                    make_float2(acc[mi][ni][2], acc[mi][ni][3]);
            }
        }
    }
}

// ---------------------------------------------------------------------------
extern "C" void kernel_launch(void* const* d_in, const int* in_sizes, int n_in,
                              void* d_out, int out_size) {
    const float* x = (const float*)d_in[0];
    const float* w = (const float*)d_in[1];
    if (n_in >= 2 && in_sizes[0] < in_sizes[1]) {  // defensive: x is the big one
        const float* t = x; x = w; w = t;
    }
    float* out = (float*)d_out;

    zero_k<<<1, 256>>>();
    count_k<<<256, 256>>>(w);
    fold_k<<<256, 256>>>(w);

    cudaFuncSetAttribute(bgemm_kernel,
                         cudaFuncAttributeMaxDynamicSharedMemorySize, SMEM_TOTAL);
    bgemm_kernel<<<GRID, THREADS, SMEM_TOTAL>>>(x, out);
}

// round 4
// speedup vs baseline: 1.5021x; 1.2413x over previous
#include <cuda_runtime.h>
#include <cuda_fp16.h>
#include <cstdint>

// ============================================================================
// y = x @ W_binT - rowmean(y),  B=131072, IN=OUT=256.
// Trick 1: fold mean into weights: W' = W_bin - c/256 (EXACT in fp16: n/256).
// Trick 2: single fp16 pass for x (rel err ~2e-4 << 1e-3).
// R4: coalesced flat-index x loads (fixes 8x L1 wavefront inflation seen in
//     R3 ncu: L1=73%), fused single prep kernel, streaming cache hints.
// ============================================================================

static constexpr int INF    = 256;
static constexpr int OUTF   = 256;
static constexpr int BATCH  = 131072;
static constexpr int MTILE  = 128;
static constexpr int NTILES = BATCH / MTILE;   // 1024
static constexpr int GRID   = 148;
static constexpr int THREADS = 256;

static constexpr int PW = 264;   // W smem pitch (halfs), conflict-free for ldmatrix
static constexpr int PA = 72;    // A smem pitch (halfs), conflict-free for ldmatrix
static constexpr int WBYTES = OUTF * PW * 2;        // 135168
static constexpr int ABYTES = MTILE * PA * 2;       // 18432
static constexpr int SMEM_TOTAL = WBYTES + 2 * ABYTES;  // 172032

__device__ __half g_wprep[OUTF * PW];   // mean-folded W', padded layout

// ---------------------------------------------------------------------------
// fused prep: one block per input column i.
// thread t reads w[t*INF + i], block-reduces the >th count, then every thread
// writes W'[t][i] = bin - cnt/256  (exact in fp16: n/256, |n|<=256).
// ---------------------------------------------------------------------------
__global__ void prep_k(const float* __restrict__ w) {
    __shared__ int red[256];
    const int i = blockIdx.x, t = threadIdx.x;
    const int bin = (w[t * INF + i] > 0.8f) ? 1 : 0;
    red[t] = bin;
    __syncthreads();
    #pragma unroll
    for (int s = 128; s > 0; s >>= 1) {
        if (t < s) red[t] += red[t + s];
        __syncthreads();
    }
    const float v = (float)bin - (float)red[0] * (1.0f / 256.0f);
    g_wprep[t * PW + i] = __float2half_rn(v);
}

// ---------------------------------------------------------------------------
// main GEMM
// ---------------------------------------------------------------------------
#define MMA_F16(c, a, b0, b1)                                                  \
    asm volatile(                                                              \
        "mma.sync.aligned.m16n8k16.row.col.f32.f16.f16.f32 "                   \
        "{%0,%1,%2,%3},{%4,%5,%6,%7},{%8,%9},{%0,%1,%2,%3};"                   \
        : "+f"((c)[0]), "+f"((c)[1]), "+f"((c)[2]), "+f"((c)[3])               \
        : "r"((a)[0]), "r"((a)[1]), "r"((a)[2]), "r"((a)[3]),                  \
          "r"(b0), "r"(b1))

#define LDSM4(r, addr)                                                         \
    asm volatile("ldmatrix.sync.aligned.m8n8.x4.shared.b16 {%0,%1,%2,%3}, [%4];" \
        : "=r"((r)[0]), "=r"((r)[1]), "=r"((r)[2]), "=r"((r)[3]) : "r"(addr))

__global__ void __launch_bounds__(THREADS, 1)
bgemm_kernel(const float* __restrict__ x, float* __restrict__ out)
{
    extern __shared__ char smem[];
    const int tid  = threadIdx.x;
    const int lane = tid & 31;
    const int wid  = tid >> 5;
    const int wm   = (wid & 1) * 64;   // warp m-offset
    const int wn   = (wid >> 1) * 64;  // warp n-offset

    // ---- resident W' into smem (whole kernel lifetime)
    {
        const uint4* src = reinterpret_cast<const uint4*>(g_wprep);
        uint4* dst = reinterpret_cast<uint4*>(smem);
        #pragma unroll
        for (int k = 0; k < WBYTES / 16 / THREADS; ++k)
            dst[tid + k * THREADS] = src[tid + k * THREADS];
    }

    uint32_t sb;
    asm("{ .reg .u64 t; cvta.to.shared.u64 t, %1; cvt.u32.u64 %0, t; }"
        : "=r"(sb) : "l"(smem));
    const uint32_t ABUF[2] = { sb + WBYTES, sb + WBYTES + ABYTES };

    // per-thread ldmatrix source offsets (bytes)
    const uint32_t aoff =
        (uint32_t)((wm + (lane & 15)) * PA + (lane >> 4) * 8) * 2u;
    const uint32_t boff =
        (uint32_t)((wn + ((lane >> 4) & 1) * 8 + (lane & 7)) * PW +
                   ((lane >> 3) & 1) * 8) * 2u;

    // flat-index x mapping: f = tid + 256*j over the 2048 float4s of a
    // 128x64 chunk: row = f>>4 (row0 = tid>>4, +16 per j), col4 = tid&15.
    const int arow0 = tid >> 4;         // 0..15
    const int acol4 = tid & 15;         // 0..15 (float4 index within 64 cols)

    float4 xr[8];

    auto ldg_chunk = [&](int nt, int nc) {
        if (nt < NTILES) {
            const float* gp = x + ((size_t)nt * MTILE + arow0) * INF
                               + nc * 64 + acol4 * 4;
            #pragma unroll
            for (int j = 0; j < 8; ++j) {
                float4 v;
                asm volatile("ld.global.cs.v4.f32 {%0,%1,%2,%3}, [%4];"
                             : "=f"(v.x), "=f"(v.y), "=f"(v.z), "=f"(v.w)
                             : "l"(gp + (size_t)j * 16 * INF));
                xr[j] = v;
            }
        }
    };
    // convert to fp16 and store; thread's j-th row = arow0 + 16*j, col4 fixed.
    auto sts_chunk = [&](uint32_t ab) {
        const uint32_t base = ab + (uint32_t)(arow0 * PA + acol4 * 4) * 2u;
        #pragma unroll
        for (int j = 0; j < 8; ++j) {
            uint32_t h0, h1;
            asm("cvt.rn.f16x2.f32 %0, %1, %2;" : "=r"(h0) : "f"(xr[j].y), "f"(xr[j].x));
            asm("cvt.rn.f16x2.f32 %0, %1, %2;" : "=r"(h1) : "f"(xr[j].w), "f"(xr[j].z));
            asm volatile("st.shared.v2.b32 [%0], {%1,%2};"
                         :: "r"(base + (uint32_t)(j * 16 * PA) * 2u), "r"(h0), "r"(h1));
        }
    };

    // prologue: chunk0 -> buf0; preload chunk1 regs
    ldg_chunk(blockIdx.x, 0);
    sts_chunk(ABUF[0]);
    ldg_chunk(blockIdx.x, 1);
    __syncthreads();

    for (int tile = blockIdx.x; tile < NTILES; tile += GRID) {
        float acc[4][8][4];
        #pragma unroll
        for (int a = 0; a < 4; ++a)
            #pragma unroll
            for (int b = 0; b < 8; ++b)
                #pragma unroll
                for (int q = 0; q < 4; ++q) acc[a][b][q] = 0.0f;

        #pragma unroll
        for (int ch = 0; ch < 4; ++ch) {
            // STS chunk ch+1 (regs already loaded) into the other buffer
            const bool has_next = !(ch == 3 && tile + GRID >= NTILES);
            if (has_next) sts_chunk(ABUF[(ch + 1) & 1]);

            // prefetch regs for chunk ch+2
            {
                int nt = tile, nc = ch + 2;
                if (nc >= 4) { nc -= 4; nt += GRID; }
                ldg_chunk(nt, nc);
            }

            // MMA over chunk ch (4 k16-steps) from buf[ch&1]
            const uint32_t AB  = ABUF[ch & 1];
            const uint32_t bko = (uint32_t)(ch * 64) * 2u;
            #pragma unroll
            for (int ks = 0; ks < 4; ++ks) {
                const uint32_t kb2 = (uint32_t)(ks * 16) * 2u;
                uint32_t bfr[4][4];
                #pragma unroll
                for (int np = 0; np < 4; ++np)
                    LDSM4(bfr[np], sb + boff + (uint32_t)(np * 16 * PW * 2) + bko + kb2);
                uint32_t af[4][4];
                #pragma unroll
                for (int mi = 0; mi < 4; ++mi)
                    LDSM4(af[mi], AB + aoff + (uint32_t)(mi * 16 * PA * 2) + kb2);
                #pragma unroll
                for (int mi = 0; mi < 4; ++mi)
                    #pragma unroll
                    for (int ni = 0; ni < 8; ++ni)
                        MMA_F16(acc[mi][ni], af[mi],
                                bfr[ni >> 1][(ni & 1) * 2],
                                bfr[ni >> 1][(ni & 1) * 2 + 1]);
            }
            __syncthreads();
        }

        // ---- epilogue: regs -> gmem (mean already folded into W')
        const int g  = lane >> 2;
        const int t4 = (lane & 3) * 2;
        #pragma unroll
        for (int mi = 0; mi < 4; ++mi) {
            size_t r0 = (size_t)(tile * MTILE + wm + mi * 16 + g) * OUTF;
            #pragma unroll
            for (int ni = 0; ni < 8; ++ni) {
                int col = wn + ni * 8 + t4;
                asm volatile("st.global.cs.v2.f32 [%0], {%1,%2};"
                             :: "l"(out + r0 + col),
                                "f"(acc[mi][ni][0]), "f"(acc[mi][ni][1]));
                asm volatile("st.global.cs.v2.f32 [%0], {%1,%2};"
                             :: "l"(out + r0 + 8 * OUTF + col),
                                "f"(acc[mi][ni][2]), "f"(acc[mi][ni][3]));
            }
        }
    }
}

// ---------------------------------------------------------------------------
extern "C" void kernel_launch(void* const* d_in, const int* in_sizes, int n_in,
                              void* d_out, int out_size) {
    const float* x = (const float*)d_in[0];
    const float* w = (const float*)d_in[1];
    if (n_in >= 2 && in_sizes[0] < in_sizes[1]) {  // defensive: x is the big one
        const float* t = x; x = w; w = t;
    }
    float* out = (float*)d_out;

    prep_k<<<256, 256>>>(w);

    cudaFuncSetAttribute(bgemm_kernel,
                         cudaFuncAttributeMaxDynamicSharedMemorySize, SMEM_TOTAL);
    bgemm_kernel<<<GRID, THREADS, SMEM_TOTAL>>>(x, out);
}